// round 1
// baseline (speedup 1.0000x reference)
#include <cuda_runtime.h>

// ---------------- problem constants ----------------
#define N0v 1000000
#define N1v 102400
#define N2v 10240
#define N3v 1024
#define E0v 1024000
#define E1v 102400
#define E2v 10240
#define DINv 128
#define DHv  256
#define DOUTv 40

// ---------------- device scratch (no allocation allowed) ----------------
__device__ float g_aggr0[N1v * DINv];        // 52.4 MB
__device__ float g_cnt0[N1v];
__device__ float g_h1[(long)N1v * DHv];      // 104.8 MB
__device__ float g_aggr1[N2v * DHv];         // 10.5 MB
__device__ float g_cnt1[N2v];
__device__ float g_h2[N2v * DHv];            // 10.5 MB
__device__ float g_aggr2[N3v * DHv];         // 1 MB
__device__ float g_cnt2[N3v];

// ---------------- small helpers ----------------
__device__ __forceinline__ void red_add_v4(float* p, float4 v) {
    asm volatile("red.global.add.v4.f32 [%0], {%1, %2, %3, %4};"
                 :: "l"(p), "f"(v.x), "f"(v.y), "f"(v.z), "f"(v.w) : "memory");
}

__device__ __forceinline__ unsigned long long pack2(float a, float b) {
    unsigned long long r;
    asm("mov.b64 %0, {%1, %2};" : "=l"(r) : "f"(a), "f"(b));
    return r;
}
__device__ __forceinline__ void ffma2(unsigned long long& d,
                                      unsigned long long a,
                                      unsigned long long b) {
    asm("fma.rn.f32x2 %0, %1, %2, %0;" : "+l"(d) : "l"(a), "l"(b));
}
__device__ __forceinline__ float2 unpack2(unsigned long long v) {
    float2 r;
    asm("mov.b64 {%0, %1}, %2;" : "=f"(r.x), "=f"(r.y) : "l"(v));
    return r;
}

// ---------------- zero kernel ----------------
__global__ void zero_kernel(float4* __restrict__ p, int n4) {
    int i = blockIdx.x * blockDim.x + threadIdx.x;
    if (i < n4) p[i] = make_float4(0.f, 0.f, 0.f, 0.f);
}

// ---------------- edge aggregation: warp per edge ----------------
// V4 = row width in float4 units (32 for 128-d, 64 for 256-d)
template <int V4>
__global__ void edge_agg_kernel(const float* __restrict__ H,
                                const int* __restrict__ src,
                                const int* __restrict__ dst,
                                float* __restrict__ aggr,
                                float* __restrict__ cnt,
                                int E) {
    int w = (blockIdx.x * blockDim.x + threadIdx.x) >> 5;
    int lane = threadIdx.x & 31;
    if (w >= E) return;
    int s = __ldg(&src[w]);
    int d = __ldg(&dst[w]);
    const float4* sp = reinterpret_cast<const float4*>(H) + (long)s * V4;
    float* dp = aggr + (long)d * (V4 * 4);
#pragma unroll
    for (int it = 0; it < V4 / 32; ++it) {
        int i = lane + it * 32;
        float4 v = sp[i];
        red_add_v4(dp + i * 4, v);
    }
    if (lane == 0) atomicAdd(cnt + d, 1.0f);
}

// ---------------- reciprocal of counts (in place) ----------------
__global__ void recip_kernel(float* __restrict__ c, int n) {
    int i = blockIdx.x * blockDim.x + threadIdx.x;
    if (i < n) c[i] = 1.0f / fmaxf(c[i], 1.0f);
}

// ---------------- fused dual GEMM:  C = act( (Aagg*rn) @ Wl + Atgt @ Wr + bias ) ----
// BM=128, BN=128, BK=16, 256 threads, 8x8 microtile via f32x2 packed FMA.
#define BM 128
#define BN 128
#define BK 16
#define ASTRIDE (BM + 4)   // 132 floats: keeps float4 alignment, dodges conflicts

__global__ __launch_bounds__(256, 2)
void gemm_fused_kernel(const float* __restrict__ Aagg,
                       const float* __restrict__ rn,
                       const float* __restrict__ Atgt,
                       const float* __restrict__ Wl,
                       const float* __restrict__ Wr,
                       const float* __restrict__ bias,
                       float* __restrict__ C,
                       int M, int K, int N, int relu) {
    __shared__ float As[BK][ASTRIDE];
    __shared__ float Bs[BK][BN];

    const int tid = threadIdx.x;
    const int tx = tid & 15;
    const int ty = tid >> 4;
    const int rowBase = blockIdx.x * BM;
    const int colBase = blockIdx.y * BN;

    // A-load mapping: thread loads 2 float4 along K of one row
    const int aRow = tid >> 1;              // 0..127
    const int aK = (tid & 1) * 8;           // 0 or 8 (then +0,+4)
    // B-load mapping: 2 float4, perfectly coalesced
    const int bK = tid >> 5;                // 0..7 (then +0,+8)
    const int bCol = (tid & 31) * 4;        // 0..124

    const float invc = rn[rowBase + aRow];

    unsigned long long acc[8][4];
#pragma unroll
    for (int i = 0; i < 8; ++i)
#pragma unroll
        for (int j = 0; j < 4; ++j) acc[i][j] = 0ull;

    for (int pass = 0; pass < 2; ++pass) {
        const float* A = pass ? Atgt : Aagg;
        const float* B = pass ? Wr : Wl;
        const float scale = pass ? 1.0f : invc;
        const int nt = K / BK;

        // prefetch tile 0
        float4 aR0 = *(const float4*)&A[(long)(rowBase + aRow) * K + aK];
        float4 aR1 = *(const float4*)&A[(long)(rowBase + aRow) * K + aK + 4];
        float4 bR0 = *(const float4*)&B[(long)bK * N + colBase + bCol];
        float4 bR1 = *(const float4*)&B[(long)(bK + 8) * N + colBase + bCol];

        for (int t = 0; t < nt; ++t) {
            __syncthreads();   // smem from previous compute is free
            As[aK + 0][aRow] = aR0.x * scale;
            As[aK + 1][aRow] = aR0.y * scale;
            As[aK + 2][aRow] = aR0.z * scale;
            As[aK + 3][aRow] = aR0.w * scale;
            As[aK + 4][aRow] = aR1.x * scale;
            As[aK + 5][aRow] = aR1.y * scale;
            As[aK + 6][aRow] = aR1.z * scale;
            As[aK + 7][aRow] = aR1.w * scale;
            *(float4*)&Bs[bK][bCol] = bR0;
            *(float4*)&Bs[bK + 8][bCol] = bR1;
            __syncthreads();

            if (t + 1 < nt) {
                int k0 = (t + 1) * BK;
                aR0 = *(const float4*)&A[(long)(rowBase + aRow) * K + k0 + aK];
                aR1 = *(const float4*)&A[(long)(rowBase + aRow) * K + k0 + aK + 4];
                bR0 = *(const float4*)&B[(long)(k0 + bK) * N + colBase + bCol];
                bR1 = *(const float4*)&B[(long)(k0 + bK + 8) * N + colBase + bCol];
            }

#pragma unroll
            for (int kk = 0; kk < BK; ++kk) {
                float4 av0 = *(const float4*)&As[kk][ty * 8];
                float4 av1 = *(const float4*)&As[kk][ty * 8 + 4];
                ulonglong2 bv0 = *(const ulonglong2*)&Bs[kk][tx * 8];
                ulonglong2 bv1 = *(const ulonglong2*)&Bs[kk][tx * 8 + 4];
                unsigned long long b0 = bv0.x, b1 = bv0.y, b2 = bv1.x, b3 = bv1.y;
                float a[8] = {av0.x, av0.y, av0.z, av0.w,
                              av1.x, av1.y, av1.z, av1.w};
#pragma unroll
                for (int i = 0; i < 8; ++i) {
                    unsigned long long pa = pack2(a[i], a[i]);
                    ffma2(acc[i][0], pa, b0);
                    ffma2(acc[i][1], pa, b1);
                    ffma2(acc[i][2], pa, b2);
                    ffma2(acc[i][3], pa, b3);
                }
            }
        }
    }

    // epilogue: + bias, optional relu, vectorized store
    float bvals[8];
#pragma unroll
    for (int j = 0; j < 8; ++j) bvals[j] = bias[colBase + tx * 8 + j];

#pragma unroll
    for (int i = 0; i < 8; ++i) {
        long r = rowBase + ty * 8 + i;
        float2 p0 = unpack2(acc[i][0]);
        float2 p1 = unpack2(acc[i][1]);
        float2 p2 = unpack2(acc[i][2]);
        float2 p3 = unpack2(acc[i][3]);
        float4 o0 = make_float4(p0.x + bvals[0], p0.y + bvals[1],
                                p1.x + bvals[2], p1.y + bvals[3]);
        float4 o1 = make_float4(p2.x + bvals[4], p2.y + bvals[5],
                                p3.x + bvals[6], p3.y + bvals[7]);
        if (relu) {
            o0.x = fmaxf(o0.x, 0.f); o0.y = fmaxf(o0.y, 0.f);
            o0.z = fmaxf(o0.z, 0.f); o0.w = fmaxf(o0.w, 0.f);
            o1.x = fmaxf(o1.x, 0.f); o1.y = fmaxf(o1.y, 0.f);
            o1.z = fmaxf(o1.z, 0.f); o1.w = fmaxf(o1.w, 0.f);
        }
        *(float4*)&C[r * N + colBase + tx * 8] = o0;
        *(float4*)&C[r * N + colBase + tx * 8 + 4] = o1;
    }
}

// ---------------- layer 2: dual GEMV (K=256 each, N=40) + log_softmax -----
__global__ void layer2_kernel(const float* __restrict__ aggr2,
                              const float* __restrict__ rn2,
                              const float* __restrict__ h2,
                              const float* __restrict__ Wl2,
                              const float* __restrict__ Wr2,
                              const float* __restrict__ b2,
                              float* __restrict__ out) {
    __shared__ float a[2 * DHv];
    __shared__ float c[DOUTv];
    __shared__ float lse;

    int row = blockIdx.x;
    int tid = threadIdx.x;   // 256 threads
    float invc = rn2[row];
    a[tid] = aggr2[(long)row * DHv + tid] * invc;
    a[DHv + tid] = h2[(long)row * DHv + tid];
    __syncthreads();

    if (tid < DOUTv) {
        float s = b2[tid];
#pragma unroll 8
        for (int k = 0; k < DHv; ++k)
            s = fmaf(a[k], __ldg(&Wl2[k * DOUTv + tid]), s);
#pragma unroll 8
        for (int k = 0; k < DHv; ++k)
            s = fmaf(a[DHv + k], __ldg(&Wr2[k * DOUTv + tid]), s);
        c[tid] = s;
    }
    __syncthreads();

    if (tid == 0) {
        float m = c[0];
#pragma unroll
        for (int j = 1; j < DOUTv; ++j) m = fmaxf(m, c[j]);
        float sum = 0.f;
#pragma unroll
        for (int j = 0; j < DOUTv; ++j) sum += expf(c[j] - m);
        lse = m + logf(sum);
    }
    __syncthreads();

    if (tid < DOUTv) out[(long)row * DOUTv + tid] = c[tid] - lse;
}

// ---------------- host launcher ----------------
extern "C" void kernel_launch(void* const* d_in, const int* in_sizes, int n_in,
                              void* d_out, int out_size) {
    const float* x   = (const float*)d_in[0];
    const int* src0  = (const int*)d_in[1];
    const int* dst0  = (const int*)d_in[2];
    const int* src1  = (const int*)d_in[3];
    const int* dst1  = (const int*)d_in[4];
    const int* src2  = (const int*)d_in[5];
    const int* dst2  = (const int*)d_in[6];
    const float* Wl0 = (const float*)d_in[7];
    const float* bl0 = (const float*)d_in[8];
    const float* Wr0 = (const float*)d_in[9];
    const float* Wl1 = (const float*)d_in[10];
    const float* bl1 = (const float*)d_in[11];
    const float* Wr1 = (const float*)d_in[12];
    const float* Wl2 = (const float*)d_in[13];
    const float* bl2 = (const float*)d_in[14];
    const float* Wr2 = (const float*)d_in[15];
    float* out = (float*)d_out;

    float *aggr0, *cnt0, *h1, *aggr1, *cnt1, *h2, *aggr2, *cnt2;
    cudaGetSymbolAddress((void**)&aggr0, g_aggr0);
    cudaGetSymbolAddress((void**)&cnt0,  g_cnt0);
    cudaGetSymbolAddress((void**)&h1,    g_h1);
    cudaGetSymbolAddress((void**)&aggr1, g_aggr1);
    cudaGetSymbolAddress((void**)&cnt1,  g_cnt1);
    cudaGetSymbolAddress((void**)&h2,    g_h2);
    cudaGetSymbolAddress((void**)&aggr2, g_aggr2);
    cudaGetSymbolAddress((void**)&cnt2,  g_cnt2);

    auto zero = [](float* p, long n) {
        int n4 = (int)(n / 4);
        zero_kernel<<<(n4 + 255) / 256, 256>>>((float4*)p, n4);
    };
    zero(aggr0, (long)N1v * DINv);
    zero(cnt0, N1v);
    zero(aggr1, (long)N2v * DHv);
    zero(cnt1, N2v);
    zero(aggr2, (long)N3v * DHv);
    zero(cnt2, N3v);

    // ----- layer 0 -----
    edge_agg_kernel<32><<<E0v / 8, 256>>>(x, src0, dst0, aggr0, cnt0, E0v);
    recip_kernel<<<(N1v + 255) / 256, 256>>>(cnt0, N1v);
    gemm_fused_kernel<<<dim3(N1v / BM, DHv / BN), 256>>>(
        aggr0, cnt0, x, Wl0, Wr0, bl0, h1, N1v, DINv, DHv, 1);

    // ----- layer 1 -----
    edge_agg_kernel<64><<<E1v / 8, 256>>>(h1, src1, dst1, aggr1, cnt1, E1v);
    recip_kernel<<<(N2v + 255) / 256, 256>>>(cnt1, N2v);
    gemm_fused_kernel<<<dim3(N2v / BM, DHv / BN), 256>>>(
        aggr1, cnt1, h1, Wl1, Wr1, bl1, h2, N2v, DHv, DHv, 1);

    // ----- layer 2 + log_softmax -----
    edge_agg_kernel<64><<<E2v / 8, 256>>>(h2, src2, dst2, aggr2, cnt2, E2v);
    recip_kernel<<<(N3v + 255) / 256, 256>>>(cnt2, N3v);
    layer2_kernel<<<N3v, 256>>>(aggr2, cnt2, h2, Wl2, Wr2, bl2, out);

    (void)in_sizes; (void)n_in; (void)out_size;
}